// round 2
// baseline (speedup 1.0000x reference)
#include <cuda_runtime.h>

// Problem constants (fixed by the dataset)
#define NMAX 100000
#define EMAX 3200000
#define GMAXG 256
#define IN_DIM 25

// Scratch (static __device__ arrays; no runtime allocation)
__device__ float g_bufA[NMAX * 64];
__device__ float g_bufB[NMAX * 64];
__device__ float g_bufC[NMAX * 64];
__device__ float g_ew[EMAX];     // per-edge norm weight dinv[src]*dinv[dst]
__device__ float g_dinv[NMAX];
__device__ int   g_deg[NMAX];
__device__ float g_pool[GMAXG * 32];
__device__ int   g_cnt[GMAXG];

// ---------------- degree / norm ----------------
__global__ void k_deg_init(int n) {
    int i = blockIdx.x * blockDim.x + threadIdx.x;
    if (i < n) g_deg[i] = 1;  // self-loop
}
__global__ void k_deg_edges(const int* __restrict__ dst, int e) {
    int i = blockIdx.x * blockDim.x + threadIdx.x;
    if (i < e) atomicAdd(&g_deg[dst[i]], 1);
}
__global__ void k_dinv(int n) {
    int i = blockIdx.x * blockDim.x + threadIdx.x;
    if (i < n) g_dinv[i] = rsqrtf((float)g_deg[i]);
}
__global__ void k_edge_w(const int* __restrict__ src, const int* __restrict__ dst, int e) {
    int i = blockIdx.x * blockDim.x + threadIdx.x;
    if (i < e) g_ew[i] = g_dinv[src[i]] * g_dinv[dst[i]];
}

// ---------------- dense layer: H = (relu?)X @ W ; O = b + H*dinv^2 ----------------
template<int K, int F, bool RELU_IN>
__global__ void k_gemm(const float* __restrict__ X, const float* __restrict__ W,
                       const float* __restrict__ b,
                       float* __restrict__ H, float* __restrict__ O, int n) {
    constexpr int NPB = 256 / F;   // nodes per block
    __shared__ float Wsh[K * F];
    __shared__ float Xsh[NPB * K];
    __shared__ float bsh[F];
    int base = blockIdx.x * NPB;
    for (int idx = threadIdx.x; idx < K * F; idx += 256) Wsh[idx] = W[idx];
    if (threadIdx.x < F) bsh[threadIdx.x] = b[threadIdx.x];
    for (int idx = threadIdx.x; idx < NPB * K; idx += 256) {
        int node = base + idx / K;
        int k = idx % K;
        float v = (node < n) ? X[(size_t)node * K + k] : 0.f;
        if (RELU_IN) v = fmaxf(v, 0.f);
        Xsh[idx] = v;
    }
    __syncthreads();
    int il = threadIdx.x / F;
    int f  = threadIdx.x % F;
    int node = base + il;
    if (node >= n) return;
    float acc = 0.f;
#pragma unroll
    for (int k = 0; k < K; k++)
        acc = fmaf(Xsh[il * K + k], Wsh[k * F + f], acc);
    H[(size_t)node * F + f] = acc;
    float di = g_dinv[node];
    O[(size_t)node * F + f] = bsh[f] + acc * di * di;  // bias + self-loop message
}

// ---------------- edge scatter: O[dst] += w_e * H[src], float4 vector RED ----------------
template<int F>
__global__ void k_scatter(const int* __restrict__ src, const int* __restrict__ dst,
                          const float* __restrict__ H, float* __restrict__ O, int e) {
    constexpr int CH = F / 4;  // float4 chunks per edge
    unsigned tid = blockIdx.x * blockDim.x + threadIdx.x;
    int ei = (int)(tid / CH);
    int c  = (int)(tid % CH);
    if (ei >= e) return;
    int s = src[ei], d = dst[ei];
    float w = g_ew[ei];
    const float4 v = *reinterpret_cast<const float4*>(&H[(size_t)s * F + c * 4]);
    float4 m;
    m.x = v.x * w; m.y = v.y * w; m.z = v.z * w; m.w = v.w * w;
    float* p = &O[(size_t)d * F + c * 4];
    asm volatile("red.global.add.v4.f32 [%0], {%1, %2, %3, %4};"
                 :: "l"(p), "f"(m.x), "f"(m.y), "f"(m.z), "f"(m.w) : "memory");
}

// ---------------- global mean pool ----------------
__global__ void k_pool_zero(int g) {
    int i = blockIdx.x * blockDim.x + threadIdx.x;
    if (i < g * 32) g_pool[i] = 0.f;
    if (i < g) g_cnt[i] = 0;
}
__global__ void k_pool(const int* __restrict__ batch, const float* __restrict__ H3, int n) {
    int tid = blockIdx.x * blockDim.x + threadIdx.x;
    int i = tid / 32, f = tid % 32;
    if (i >= n) return;
    int g = batch[i];
    atomicAdd(&g_pool[g * 32 + f], fmaxf(H3[(size_t)i * 32 + f], 0.f));
    if (f == 0) atomicAdd(&g_cnt[g], 1);
}

// ---------------- MLP head ----------------
__global__ void k_head(const float* __restrict__ Wh1, const float* __restrict__ bh1,
                       const float* __restrict__ Wh2, const float* __restrict__ bh2,
                       float* __restrict__ y, int G) {
    __shared__ float W1s[32 * 32], b1s[32], W2s[32];
    int t = threadIdx.x;
    for (int idx = t; idx < 1024; idx += blockDim.x) W1s[idx] = Wh1[idx];
    if (t < 32) { b1s[t] = bh1[t]; W2s[t] = Wh2[t]; }
    __syncthreads();
    if (t >= G) return;
    float inv = 1.f / fmaxf((float)g_cnt[t], 1.f);
    float row[32];
#pragma unroll
    for (int k = 0; k < 32; k++) row[k] = g_pool[t * 32 + k] * inv;
    float acc = bh2[0];
#pragma unroll
    for (int j = 0; j < 32; j++) {
        float s = b1s[j];
#pragma unroll
        for (int k = 0; k < 32; k++) s = fmaf(row[k], W1s[k * 32 + j], s);
        acc = fmaf(fmaxf(s, 0.f), W2s[j], acc);
    }
    y[t] = acc;
}

extern "C" void kernel_launch(void* const* d_in, const int* in_sizes, int n_in,
                              void* d_out, int out_size) {
    const float* x   = (const float*)d_in[0];
    const int*   ei  = (const int*)d_in[1];
    const int*   bat = (const int*)d_in[2];
    const float* W1  = (const float*)d_in[3];
    const float* b1  = (const float*)d_in[4];
    const float* W2  = (const float*)d_in[5];
    const float* b2  = (const float*)d_in[6];
    const float* W3  = (const float*)d_in[7];
    const float* b3  = (const float*)d_in[8];
    const float* Wh1 = (const float*)d_in[9];
    const float* bh1 = (const float*)d_in[10];
    const float* Wh2 = (const float*)d_in[11];
    const float* bh2 = (const float*)d_in[12];
    float* y = (float*)d_out;

    int n = in_sizes[0] / IN_DIM;
    int e = in_sizes[1] / 2;
    int G = out_size;
    const int* src = ei;
    const int* dst = ei + e;

    float *A, *B, *C;
    cudaGetSymbolAddress((void**)&A, g_bufA);
    cudaGetSymbolAddress((void**)&B, g_bufB);
    cudaGetSymbolAddress((void**)&C, g_bufC);

    const int T = 256;
    auto blocks = [](long long work, int t) { return (int)((work + t - 1) / t); };

    // degrees + per-edge weights (reused by all 3 layers)
    k_deg_init <<<blocks(n, T), T>>>(n);
    k_deg_edges<<<blocks(e, T), T>>>(dst, e);
    k_dinv     <<<blocks(n, T), T>>>(n);
    k_edge_w   <<<blocks(e, T), T>>>(src, dst, e);

    // Layer 1: x[N,25] -> (h=A, out=B); scatter A into B
    k_gemm<IN_DIM, 64, false><<<blocks((long long)n * 64, T) , T>>>(x, W1, b1, A, B, n);
    k_scatter<64><<<blocks((long long)e * 16, T), T>>>(src, dst, A, B, e);

    // Layer 2: relu(B)[N,64] -> (h=A, out=C); scatter A into C
    k_gemm<64, 64, true><<<blocks((long long)n * 64, T), T>>>(B, W2, b2, A, C, n);
    k_scatter<64><<<blocks((long long)e * 16, T), T>>>(src, dst, A, C, e);

    // Layer 3: relu(C)[N,64] -> (h=A, out=B, F=32); scatter A into B
    k_gemm<64, 32, true><<<blocks((long long)n * 32, T), T>>>(C, W3, b3, A, B, n);
    k_scatter<32><<<blocks((long long)e * 8, T), T>>>(src, dst, A, B, e);

    // Global mean pool (relu folded in) + head
    k_pool_zero<<<blocks(G * 32, T), T>>>(G);
    k_pool<<<blocks((long long)n * 32, T), T>>>(bat, B, n);
    k_head<<<1, 256>>>(Wh1, bh1, Wh2, bh2, y, G);
}

// round 4
// speedup vs baseline: 1.5935x; 1.5935x over previous
#include <cuda_runtime.h>

#define NMAX 100000
#define EMAX 3200000
#define GMAXG 256
#define IN_DIM 25

// Scratch
__device__ float g_bufA[NMAX * 64];
__device__ float g_bufB[NMAX * 64];
__device__ float g_bufC[NMAX * 64];
__device__ int2  g_csr[EMAX];        // {src, weight-bits} sorted by dst
__device__ int   g_rowptr[NMAX + 2];
__device__ int   g_len[NMAX + 1];
__device__ int   g_cur[NMAX];
__device__ int   g_bsum[512];
__device__ float g_dinv[NMAX];
__device__ float g_pool[GMAXG * 32];
__device__ int   g_cnt[GMAXG];

// ---------------- init / degree ----------------
__global__ void k_init(int n1) {
    int i = blockIdx.x * blockDim.x + threadIdx.x;
    if (i < n1) g_len[i] = 0;
    if (i < NMAX) g_cur[i] = 0;
}
__global__ void k_count(const int* __restrict__ dst, int e) {
    int i = blockIdx.x * blockDim.x + threadIdx.x;
    if (i < e) atomicAdd(&g_len[dst[i]], 1);
}
__global__ void k_dinv(int n) {
    int i = blockIdx.x * blockDim.x + threadIdx.x;
    if (i < n) g_dinv[i] = rsqrtf((float)(g_len[i] + 1));  // +1 self-loop
}

// ---------------- exclusive scan of g_len -> g_rowptr ----------------
__global__ void k_scan1(int n1) {
    __shared__ int sw[8];
    int gid = blockIdx.x * 256 + threadIdx.x;
    int lane = threadIdx.x & 31, wid = threadIdx.x >> 5;
    int v = (gid < n1) ? g_len[gid] : 0;
    int x = v;
    for (int o = 1; o < 32; o <<= 1) { int t = __shfl_up_sync(~0u, x, o); if (lane >= o) x += t; }
    if (lane == 31) sw[wid] = x;
    __syncthreads();
    if (wid == 0) {
        int y = (lane < 8) ? sw[lane] : 0;
        for (int o = 1; o < 8; o <<= 1) { int t = __shfl_up_sync(~0u, y, o); if (lane >= o) y += t; }
        if (lane < 8) sw[lane] = y;
    }
    __syncthreads();
    int off = wid ? sw[wid - 1] : 0;
    if (gid < n1) g_rowptr[gid] = x - v + off;
    if (threadIdx.x == 255) g_bsum[blockIdx.x] = off + x;
}
__global__ void k_scan2(int nb) {   // single block, 512 threads
    __shared__ int sw[16];
    int t = threadIdx.x, lane = t & 31, wid = t >> 5;
    int v = (t < nb) ? g_bsum[t] : 0;
    int x = v;
    for (int o = 1; o < 32; o <<= 1) { int q = __shfl_up_sync(~0u, x, o); if (lane >= o) x += q; }
    if (lane == 31) sw[wid] = x;
    __syncthreads();
    if (wid == 0) {
        int y = (lane < 16) ? sw[lane] : 0;
        for (int o = 1; o < 16; o <<= 1) { int q = __shfl_up_sync(~0u, y, o); if (lane >= o) y += q; }
        if (lane < 16) sw[lane] = y;
    }
    __syncthreads();
    int off = wid ? sw[wid - 1] : 0;
    if (t < nb) g_bsum[t] = x - v + off;   // exclusive
}
__global__ void k_scan3(int n1) {
    int gid = blockIdx.x * 256 + threadIdx.x;
    if (gid < n1) g_rowptr[gid] += g_bsum[blockIdx.x];
}

// ---------------- place edges into CSR ----------------
__global__ void k_place(const int* __restrict__ src, const int* __restrict__ dst, int e) {
    int i = blockIdx.x * blockDim.x + threadIdx.x;
    if (i >= e) return;
    int s = src[i], d = dst[i];
    int pos = g_rowptr[d] + atomicAdd(&g_cur[d], 1);
    g_csr[pos] = make_int2(s, __float_as_int(g_dinv[s] * g_dinv[d]));
}

// ---------------- pad x [N,25] -> [N,32] ----------------
__global__ void k_pad(const float* __restrict__ x, float* __restrict__ P, int n) {
    int tid = blockIdx.x * blockDim.x + threadIdx.x;
    int i = tid >> 5, f = tid & 31;
    if (i >= n) return;
    P[(size_t)i * 32 + f] = (f < IN_DIM) ? x[(size_t)i * IN_DIM + f] : 0.f;
}

// ---------------- pull aggregation: out[i] = sum_j w_ij * act(in[j]) + dinv_i^2 * act(in[i]) (+b)
template<int F, bool RELU, bool BIAS>
__global__ void k_pull(const float* __restrict__ in, float* __restrict__ out,
                       const float* __restrict__ b, int n) {
    int warp = (blockIdx.x * blockDim.x + threadIdx.x) >> 5;
    int lane = threadIdx.x & 31;
    if (warp >= n) return;
    int beg = g_rowptr[warp], end = g_rowptr[warp + 1];
    float a0 = 0.f, a1 = 0.f;
    int base = beg;
    for (; base + 32 <= end; base += 32) {
        int2 m = g_csr[base + lane];
#pragma unroll
        for (int j = 0; j < 32; j++) {
            int s = __shfl_sync(~0u, m.x, j);
            float w = __int_as_float(__shfl_sync(~0u, m.y, j));
            float v0 = __ldg(&in[(size_t)s * F + lane]);
            if (RELU) v0 = fmaxf(v0, 0.f);
            a0 = fmaf(w, v0, a0);
            if (F == 64) {
                float v1 = __ldg(&in[(size_t)s * F + 32 + lane]);
                if (RELU) v1 = fmaxf(v1, 0.f);
                a1 = fmaf(w, v1, a1);
            }
        }
    }
    int rem = end - base;
    if (rem > 0) {
        int2 m = (lane < rem) ? g_csr[base + lane] : make_int2(0, 0);
        for (int j = 0; j < rem; j++) {
            int s = __shfl_sync(~0u, m.x, j);
            float w = __int_as_float(__shfl_sync(~0u, m.y, j));
            float v0 = __ldg(&in[(size_t)s * F + lane]);
            if (RELU) v0 = fmaxf(v0, 0.f);
            a0 = fmaf(w, v0, a0);
            if (F == 64) {
                float v1 = __ldg(&in[(size_t)s * F + 32 + lane]);
                if (RELU) v1 = fmaxf(v1, 0.f);
                a1 = fmaf(w, v1, a1);
            }
        }
    }
    float di = g_dinv[warp], ws = di * di;
    float s0 = in[(size_t)warp * F + lane];
    if (RELU) s0 = fmaxf(s0, 0.f);
    a0 = fmaf(ws, s0, a0);
    if (F == 64) {
        float s1 = in[(size_t)warp * F + 32 + lane];
        if (RELU) s1 = fmaxf(s1, 0.f);
        a1 = fmaf(ws, s1, a1);
    }
    if (BIAS) { a0 += b[lane]; if (F == 64) a1 += b[32 + lane]; }
    out[(size_t)warp * F + lane] = a0;
    if (F == 64) out[(size_t)warp * F + 32 + lane] = a1;
}

// ---------------- dense: O = act(X) @ W (+b) ----------------
template<int K, int F, bool RELU, bool BIAS>
__global__ void k_gemm(const float* __restrict__ X, const float* __restrict__ W,
                       const float* __restrict__ b, float* __restrict__ O,
                       int n, int kreal) {
    constexpr int NPB = 256 / F;
    __shared__ float Wsh[K * F];
    __shared__ float Xsh[NPB * K];
    __shared__ float bsh[F];
    int base = blockIdx.x * NPB;
    for (int idx = threadIdx.x; idx < K * F; idx += 256) {
        int k = idx / F;
        Wsh[idx] = (k < kreal) ? W[idx] : 0.f;
    }
    if (BIAS && threadIdx.x < F) bsh[threadIdx.x] = b[threadIdx.x];
    for (int idx = threadIdx.x; idx < NPB * K; idx += 256) {
        int node = base + idx / K;
        int k = idx % K;
        float v = (node < n) ? X[(size_t)node * K + k] : 0.f;
        if (RELU) v = fmaxf(v, 0.f);
        Xsh[idx] = v;
    }
    __syncthreads();
    int il = threadIdx.x / F, f = threadIdx.x % F;
    int node = base + il;
    if (node >= n) return;
    float acc = 0.f;
#pragma unroll
    for (int k = 0; k < K; k++)
        acc = fmaf(Xsh[il * K + k], Wsh[k * F + f], acc);
    O[(size_t)node * F + f] = BIAS ? (acc + bsh[f]) : acc;
}

// ---------------- mean pool over sorted batch (relu folded) ----------------
__global__ void k_pool_zero(int g) {
    int i = blockIdx.x * blockDim.x + threadIdx.x;
    if (i < g * 32) g_pool[i] = 0.f;
    if (i < g) g_cnt[i] = 0;
}
__global__ void k_pool(const int* __restrict__ batch, const float* __restrict__ H, int n) {
    __shared__ float sm[256];
    int f = threadIdx.x & 31, r = threadIdx.x >> 5;
    int base = blockIdx.x * 32;
    if (base >= n) return;
    int last = min(base + 31, n - 1);
    if (batch[base] == batch[last]) {
        float a = 0.f;
#pragma unroll
        for (int k = 0; k < 4; k++) {
            int i = base + r * 4 + k;
            if (i < n) a += fmaxf(H[(size_t)i * 32 + f], 0.f);
        }
        sm[r * 32 + f] = a;
        __syncthreads();
        for (int s = 4; s >= 1; s >>= 1) {
            if (r < s) sm[r * 32 + f] += sm[(r + s) * 32 + f];
            __syncthreads();
        }
        if (r == 0) atomicAdd(&g_pool[batch[base] * 32 + f], sm[f]);
        if (threadIdx.x == 0) atomicAdd(&g_cnt[batch[base]], last - base + 1);
    } else {
        for (int k = 0; k < 4; k++) {
            int i = base + r * 4 + k;
            if (i < n) {
                int g = batch[i];
                atomicAdd(&g_pool[g * 32 + f], fmaxf(H[(size_t)i * 32 + f], 0.f));
                if (f == 0) atomicAdd(&g_cnt[g], 1);
            }
        }
    }
}

// ---------------- MLP head ----------------
__global__ void k_head(const float* __restrict__ Wh1, const float* __restrict__ bh1,
                       const float* __restrict__ Wh2, const float* __restrict__ bh2,
                       float* __restrict__ y, int G) {
    __shared__ float W1s[32 * 32], b1s[32], W2s[32];
    int t = threadIdx.x;
    for (int idx = t; idx < 1024; idx += blockDim.x) W1s[idx] = Wh1[idx];
    if (t < 32) { b1s[t] = bh1[t]; W2s[t] = Wh2[t]; }
    __syncthreads();
    if (t >= G) return;
    float inv = 1.f / fmaxf((float)g_cnt[t], 1.f);
    float row[32];
#pragma unroll
    for (int k = 0; k < 32; k++) row[k] = g_pool[t * 32 + k] * inv;
    float acc = bh2[0];
#pragma unroll
    for (int j = 0; j < 32; j++) {
        float s = b1s[j];
#pragma unroll
        for (int k = 0; k < 32; k++) s = fmaf(row[k], W1s[k * 32 + j], s);
        acc = fmaf(fmaxf(s, 0.f), W2s[j], acc);
    }
    y[t] = acc;
}

extern "C" void kernel_launch(void* const* d_in, const int* in_sizes, int n_in,
                              void* d_out, int out_size) {
    const float* x   = (const float*)d_in[0];
    const int*   ei  = (const int*)d_in[1];
    const int*   bat = (const int*)d_in[2];
    const float* W1  = (const float*)d_in[3];
    const float* b1  = (const float*)d_in[4];
    const float* W2  = (const float*)d_in[5];
    const float* b2  = (const float*)d_in[6];
    const float* W3  = (const float*)d_in[7];
    const float* b3  = (const float*)d_in[8];
    const float* Wh1 = (const float*)d_in[9];
    const float* bh1 = (const float*)d_in[10];
    const float* Wh2 = (const float*)d_in[11];
    const float* bh2 = (const float*)d_in[12];
    float* y = (float*)d_out;

    int n = in_sizes[0] / IN_DIM;
    int e = in_sizes[1] / 2;
    int G = out_size;
    int n1 = n + 1;
    const int* src = ei;
    const int* dst = ei + e;

    float *A, *B, *C;
    cudaGetSymbolAddress((void**)&A, g_bufA);
    cudaGetSymbolAddress((void**)&B, g_bufB);
    cudaGetSymbolAddress((void**)&C, g_bufC);

    const int T = 256;
    auto blk = [](long long w, int t) { return (int)((w + t - 1) / t); };
    int scan_blocks = blk(n1, 256);

    // ---- CSR build (counting sort by dst) ----
    k_init <<<blk(n1, T), T>>>(n1);
    k_count<<<blk(e, T), T>>>(dst, e);
    k_dinv <<<blk(n, T), T>>>(n);
    k_scan1<<<scan_blocks, 256>>>(n1);
    k_scan2<<<1, 512>>>(scan_blocks);
    k_scan3<<<scan_blocks, 256>>>(n1);
    k_place<<<blk(e, T), T>>>(src, dst, e);

    // ---- layer pipeline:  A@(XW) == (A@X)W ----
    // pad x -> A[N,32]
    k_pad<<<blk((long long)n * 32, T), T>>>(x, A, n);
    // agg1 = pull(A) -> C[N,32]
    k_pull<32, false, false><<<blk((long long)n * 32, T), T>>>(A, C, nullptr, n);
    // h1 = agg1@W1 + b1 -> B[N,64]
    k_gemm<32, 64, false, true><<<blk(n, 4), 256>>>(C, W1, b1, B, n, IN_DIM);
    // agg2 = pull(relu(B)) -> C[N,64]
    k_pull<64, true, false><<<blk((long long)n * 32, T), T>>>(B, C, nullptr, n);
    // h2 = agg2@W2 + b2 -> A[N,64]
    k_gemm<64, 64, false, true><<<blk(n, 4), 256>>>(C, W2, b2, A, n, 64);
    // T = relu(A)@W3 -> C[N,32]
    k_gemm<64, 32, true, false><<<blk(n, 8), 256>>>(A, W3, nullptr, C, n, 64);
    // out3 = pull(C) + b3 -> A[N,32]
    k_pull<32, false, true><<<blk((long long)n * 32, T), T>>>(C, A, b3, n);

    // ---- pool + head ----
    k_pool_zero<<<blk(G * 32, T), T>>>(G);
    k_pool<<<blk(n, 32), 256>>>(bat, A, n);
    k_head<<<1, 256>>>(Wh1, bh1, Wh2, bh2, y, G);
}